// round 8
// baseline (speedup 1.0000x reference)
#include <cuda_runtime.h>
#include <cuda_bf16.h>
#include <math.h>
#include <stdint.h>

// ---------------------------------------------------------------------------
// ReDrafterHead: 2-layer GRU draft head + big vocab projection.
// B=64, HIDDEN=4096, DH=512, VOCAB=50257, NUM_DRAFT=4.
//
// Round 8:
//  - logits: A-stationary persistent kernel (148 CTAs, A panel resident in
//    SMEM, only B streamed per slab) -> removes per-slab A cp.async storm.
//  - gru: gi/gh CTA split (half the A LDG), gates staged via global,
//    separate combine phase; step-0 gi GEMM skipped (x == 0).
// ---------------------------------------------------------------------------

#define B_      64
#define HID     4096
#define DH      512
#define VOCAB   50257
#define NDRAFT  4
#define GRIDN   128

__device__ float g_h0[B_ * DH];
__device__ float g_h1[B_ * DH];
__device__ float g_x[B_ * DH];
__device__ float g_gates[B_ * 3072];        // [m][gi r,z,n | gh r,z,n] x 512
__device__ float g_part[16 * B_ * DH];      // ip split-K partials
__device__ __nv_bfloat16 g_Ahi[B_ * NDRAFT * DH];
__device__ __nv_bfloat16 g_Alo[B_ * NDRAFT * DH];
__device__ unsigned int g_bcount;           // monotonic barrier counter

__device__ __forceinline__ float sigmoidf_(float v) { return 1.0f / (1.0f + __expf(-v)); }

__device__ __forceinline__ uint32_t pack_bf16x2(__nv_bfloat16 lo, __nv_bfloat16 hi) {
    return ((uint32_t)__bfloat16_as_ushort(hi) << 16) | (uint32_t)__bfloat16_as_ushort(lo);
}
__device__ __forceinline__ uint32_t smem_to_u32(const void* p) {
    uint32_t a;
    asm("{ .reg .u64 t; cvta.to.shared.u64 t, %1; cvt.u32.u64 %0, t; }" : "=r"(a) : "l"(p));
    return a;
}
__device__ __forceinline__ void ldsm4(uint32_t* r, uint32_t addr) {
    asm volatile("ldmatrix.sync.aligned.m8n8.x4.shared.b16 {%0,%1,%2,%3}, [%4];"
        : "=r"(r[0]), "=r"(r[1]), "=r"(r[2]), "=r"(r[3]) : "r"(addr));
}
__device__ __forceinline__ void mma16816(float* d, const uint32_t* a, const uint32_t* b) {
    asm volatile("mma.sync.aligned.m16n8k16.row.col.f32.bf16.bf16.f32 "
        "{%0,%1,%2,%3}, {%4,%5,%6,%7}, {%8,%9}, {%0,%1,%2,%3};"
        : "+f"(d[0]), "+f"(d[1]), "+f"(d[2]), "+f"(d[3])
        : "r"(a[0]), "r"(a[1]), "r"(a[2]), "r"(a[3]), "r"(b[0]), "r"(b[1]));
}

// Grid-wide barrier: monotonic counter (graph-replay safe; GRIDN co-resident).
__device__ __forceinline__ void grid_barrier(int tid) {
    __syncthreads();
    if (tid == 0) {
        __threadfence();
        unsigned int old = atomicAdd(&g_bcount, 1u);
        unsigned int target = (old / GRIDN + 1u) * GRIDN;
        unsigned int v;
        do {
            asm volatile("ld.acquire.gpu.global.u32 %0, [%1];" : "=r"(v) : "l"(&g_bcount));
        } while (v < target);
    }
    __syncthreads();
}

// ---------------------------------------------------------------------------
struct SmemIP { float As[32][64]; float Ws[32][64]; };
struct SmemG2 { float A[64][36]; float W[24][36]; };

// GEMM 64 x 24 x 512: one of gi/gh for j-range [jb, jb+8).
// W row rr in 0..23 -> global gate row (rr>>3)*512 + jb + (rr&7).
// Result written to g_gates[m][ghOff + (c>>3)*512 + jb + (c&7)].
__device__ __forceinline__ void gate_gemm(
    SmemG2& s, int tid, int jb, int ghOff,
    const float* __restrict__ A, const float* __restrict__ W)
{
    const int r0 = (tid >> 3) * 2;          // rows r0, r0+1
    const int c0 = (tid & 7) * 3;           // cols c0..c0+2
    float acc[2][3] = {};

    float4 pA[2], pW;
    const int frow = tid >> 3;              // 0..31 (+32)
    const int fc4  = (tid & 7) * 4;         // 0..28
    const int wr   = tid >> 3;              // W slab row (tid<192)
    const long wgr = (long)((wr >> 3) * 512 + jb + (wr & 7)) * DH + fc4;

    auto fetch = [&](int kt) {
        pA[0] = *reinterpret_cast<const float4*>(&A[frow * DH + kt + fc4]);
        pA[1] = *reinterpret_cast<const float4*>(&A[(frow + 32) * DH + kt + fc4]);
        if (tid < 192) pW = *reinterpret_cast<const float4*>(&W[wgr + kt]);
    };
    auto stage = [&]() {
        *reinterpret_cast<float4*>(&s.A[frow][fc4])      = pA[0];
        *reinterpret_cast<float4*>(&s.A[frow + 32][fc4]) = pA[1];
        if (tid < 192) *reinterpret_cast<float4*>(&s.W[wr][fc4]) = pW;
    };

    fetch(0);
    for (int kt = 0; kt < DH; kt += 32) {
        __syncthreads();
        stage();
        __syncthreads();
        if (kt + 32 < DH) fetch(kt + 32);
        #pragma unroll
        for (int k = 0; k < 32; k += 4) {
            float4 w0 = *reinterpret_cast<const float4*>(&s.W[c0 + 0][k]);
            float4 w1 = *reinterpret_cast<const float4*>(&s.W[c0 + 1][k]);
            float4 w2 = *reinterpret_cast<const float4*>(&s.W[c0 + 2][k]);
            #pragma unroll
            for (int r = 0; r < 2; r++) {
                float4 a = *reinterpret_cast<const float4*>(&s.A[r0 + r][k]);
                acc[r][0] += a.x * w0.x + a.y * w0.y + a.z * w0.z + a.w * w0.w;
                acc[r][1] += a.x * w1.x + a.y * w1.y + a.z * w1.z + a.w * w1.w;
                acc[r][2] += a.x * w2.x + a.y * w2.y + a.z * w2.z + a.w * w2.w;
            }
        }
    }
    #pragma unroll
    for (int r = 0; r < 2; r++)
        #pragma unroll
        for (int cc = 0; cc < 3; cc++) {
            int cx = c0 + cc;
            int col = ghOff + (cx >> 3) * 512 + jb + (cx & 7);
            g_gates[(r0 + r) * 3072 + col] = acc[r][cc];
        }
}

__device__ __forceinline__ void gate_zero(int tid, int jb)
{
    const int r0 = (tid >> 3) * 2;
    const int c0 = (tid & 7) * 3;
    #pragma unroll
    for (int r = 0; r < 2; r++)
        #pragma unroll
        for (int cc = 0; cc < 3; cc++) {
            int cx = c0 + cc;
            int col = (cx >> 3) * 512 + jb + (cx & 7);
            g_gates[(r0 + r) * 3072 + col] = 0.f;
        }
}

// combine: one h-element per thread (32768 threads exactly).
__device__ __forceinline__ void gru_combine_ph(
    int c, int tid, const float* __restrict__ bih, const float* __restrict__ bhh,
    float* __restrict__ h, bool writeA, int step,
    const int* __restrict__ tids, const float* __restrict__ embed)
{
    int idx = c * 256 + tid;
    int m = idx >> 9, j = idx & 511;
    const float* G = g_gates + m * 3072;
    float r = sigmoidf_(G[j]        + bih[j]        + G[1536 + j] + bhh[j]);
    float z = sigmoidf_(G[512 + j]  + bih[512 + j]  + G[2048 + j] + bhh[512 + j]);
    float n = tanhf(G[1024 + j] + bih[1024 + j] + r * (G[2560 + j] + bhh[1024 + j]));
    float hn = (1.f - z) * n + z * h[idx];
    h[idx] = hn;
    if (writeA) {
        int o = (m * NDRAFT + step) * DH + j;
        __nv_bfloat16 hi = __float2bfloat16(hn);
        g_Ahi[o] = hi;
        g_Alo[o] = __float2bfloat16(hn - __bfloat162float(hi));
        if (step < NDRAFT - 1)
            g_x[idx] = embed[(long)tids[m * NDRAFT + step] * DH + j];
    }
}

// ---------------------------------------------------------------------------
__global__ __launch_bounds__(256) void gru_fused(
    const float* __restrict__ hidden, const int* __restrict__ tids,
    const float* __restrict__ ip_w,  const float* __restrict__ ip_b,
    const float* __restrict__ w_ih0, const float* __restrict__ w_hh0,
    const float* __restrict__ b_ih0, const float* __restrict__ b_hh0,
    const float* __restrict__ w_ih1, const float* __restrict__ w_hh1,
    const float* __restrict__ b_ih1, const float* __restrict__ b_hh1,
    const float* __restrict__ embed)
{
    __shared__ union { SmemIP ip; SmemG2 g; } sm;
    const int tid = threadIdx.x;
    const int c = blockIdx.x;

    // ---- phase 0: input projection partials (64x64 n-tile, 256-k slice) ----
    {
        const int n0 = (c & 7) * 64;
        const int kbase = (c >> 3) * 256;
        const int ty = tid >> 4, tx = tid & 15;
        float acc[4][4] = {};
        for (int kt = 0; kt < 256; kt += 32) {
            #pragma unroll
            for (int i = 0; i < 2; i++) {
                int f = tid + i * 256;
                int m = f >> 3;
                int kq = (f & 7) << 2;
                float4 va = *reinterpret_cast<const float4*>(&hidden[m * HID + kbase + kt + kq]);
                sm.ip.As[kq + 0][m] = va.x; sm.ip.As[kq + 1][m] = va.y;
                sm.ip.As[kq + 2][m] = va.z; sm.ip.As[kq + 3][m] = va.w;
                float4 vw = *reinterpret_cast<const float4*>(&ip_w[(n0 + m) * HID + kbase + kt + kq]);
                sm.ip.Ws[kq + 0][m] = vw.x; sm.ip.Ws[kq + 1][m] = vw.y;
                sm.ip.Ws[kq + 2][m] = vw.z; sm.ip.Ws[kq + 3][m] = vw.w;
            }
            __syncthreads();
            #pragma unroll
            for (int kk = 0; kk < 32; kk++) {
                float a[4], b[4];
                #pragma unroll
                for (int i = 0; i < 4; i++) { a[i] = sm.ip.As[kk][ty * 4 + i]; b[i] = sm.ip.Ws[kk][tx * 4 + i]; }
                #pragma unroll
                for (int i = 0; i < 4; i++)
                    #pragma unroll
                    for (int j = 0; j < 4; j++) acc[i][j] += a[i] * b[j];
            }
            __syncthreads();
        }
        float* part = g_part + (c >> 3) * (B_ * DH);
        #pragma unroll
        for (int i = 0; i < 4; i++)
            #pragma unroll
            for (int j = 0; j < 4; j++)
                part[(ty * 4 + i) * DH + n0 + tx * 4 + j] = acc[i][j];
    }
    grid_barrier(tid);

    // ---- phase 1: reduce 16 partials + bias ----
    {
        int idx = c * 256 + tid;
        float s = 0.f;
        #pragma unroll
        for (int p = 0; p < 16; p++) s += g_part[p * (B_ * DH) + idx];
        s += ip_b[idx & (DH - 1)];
        g_h0[idx] = s;
        g_h1[idx] = s;
    }
    grid_barrier(tid);

    // ---- 4 draft steps x 2 GRU layers; CTA is a gi- or gh-worker ----
    const bool isGH = (c >= 64);
    const int  jb   = (isGH ? c - 64 : c) * 8;
    const int  ghOff = isGH ? 1536 : 0;

    for (int step = 0; step < NDRAFT; step++) {
        // layer 0 gemm: gi = x @ w_ih0^T  |  gh = h0 @ w_hh0^T
        if (!isGH && step == 0) gate_zero(tid, jb);
        else gate_gemm(sm.g, tid, jb, ghOff,
                       isGH ? g_h0 : g_x, isGH ? w_hh0 : w_ih0);
        grid_barrier(tid);
        gru_combine_ph(c, tid, b_ih0, b_hh0, g_h0, false, step, tids, embed);
        grid_barrier(tid);
        // layer 1 gemm: gi = h0_new @ w_ih1^T  |  gh = h1 @ w_hh1^T
        gate_gemm(sm.g, tid, jb, ghOff,
                  isGH ? g_h1 : g_h0, isGH ? w_hh1 : w_ih1);
        grid_barrier(tid);
        gru_combine_ph(c, tid, b_ih1, b_hh1, g_h1, true, step, tids, embed);
        grid_barrier(tid);
    }
}

// ---------------------------------------------------------------------------
// Logits GEMM: A-stationary persistent. 148 CTAs, 1/SM.
// CTA owns m-quarter q = c&3 (64 rows); A panel (hi+lo bf16, row stride
// 1040B -> conflict-free ldsm) resident in SMEM. Jobs: n-tiles of 128,
// j = (c>>2) + 37*t. 8 warps = 2M x 4N, warp tile 32 x 32, 3-term split.
// ---------------------------------------------------------------------------
#define APSTRB 1040                       // A panel row stride bytes
#define APH_OFF 0
#define APL_OFF 66560
#define ROWB 80
#define LBH_OFF(s) (133120 + (s) * 10240)
#define LBL_OFF(s) (153600 + (s) * 10240)
#define LOGITS_SMEM 174080
#define NJOBS 393

__global__ __launch_bounds__(256, 1) void logits_mma(const float* __restrict__ W,
                                                     float* __restrict__ out)
{
    extern __shared__ char smem[];
    const uint32_t sbase = smem_to_u32(smem);
    const int tid  = threadIdx.x;
    const int lane = tid & 31;
    const int w    = tid >> 5;
    const int wm   = w >> 2;   // 0..1
    const int wn   = w & 3;    // 0..3
    const int q    = blockIdx.x & 3;
    const int m0   = q * 64;

    // ---- load A panel once (64 rows x 512 K, hi + lo) ----
    #pragma unroll
    for (int i = 0; i < 16; i++) {
        int f = tid + i * 256;           // 0..4095
        int row = f >> 6;                // 0..63
        int ch  = f & 63;                // 16B chunk in 1024B row
        uint4 vh = *reinterpret_cast<const uint4*>(&g_Ahi[(m0 + row) * DH + ch * 8]);
        *reinterpret_cast<uint4*>(smem + APH_OFF + row * APSTRB + ch * 16) = vh;
        uint4 vl = *reinterpret_cast<const uint4*>(&g_Alo[(m0 + row) * DH + ch * 8]);
        *reinterpret_cast<uint4*>(smem + APL_OFF + row * APSTRB + ch * 16) = vl;
    }
    __syncthreads();

    float4 breg[4];

    auto ldg_B = [&](int n0, int c) {
        const int k0 = c * 32;
        #pragma unroll
        for (int i = 0; i < 4; i++) {
            int idx = tid + i * 256;     // 0..1023
            int row = idx >> 3;          // 0..127
            int col = (idx & 7) * 4;
            int vr = n0 + row;
            breg[i] = (vr < VOCAB)
                ? *reinterpret_cast<const float4*>(&W[(long)vr * DH + k0 + col])
                : make_float4(0.f, 0.f, 0.f, 0.f);
        }
    };
    auto sts_B = [&](int s) {
        #pragma unroll
        for (int i = 0; i < 4; i++) {
            int idx = tid + i * 256;
            int row = idx >> 3;
            int col = (idx & 7) * 4;
            float4 v = breg[i];
            __nv_bfloat16 hx = __float2bfloat16(v.x), hy = __float2bfloat16(v.y);
            __nv_bfloat16 hz = __float2bfloat16(v.z), hw = __float2bfloat16(v.w);
            __nv_bfloat16 lx = __float2bfloat16(v.x - __bfloat162float(hx));
            __nv_bfloat16 ly = __float2bfloat16(v.y - __bfloat162float(hy));
            __nv_bfloat16 lz = __float2bfloat16(v.z - __bfloat162float(hz));
            __nv_bfloat16 lw = __float2bfloat16(v.w - __bfloat162float(hw));
            uint2 ph, pl;
            ph.x = pack_bf16x2(hx, hy); ph.y = pack_bf16x2(hz, hw);
            pl.x = pack_bf16x2(lx, ly); pl.y = pack_bf16x2(lz, lw);
            *reinterpret_cast<uint2*>(smem + LBH_OFF(s) + row * ROWB + col * 2) = ph;
            *reinterpret_cast<uint2*>(smem + LBL_OFF(s) + row * ROWB + col * 2) = pl;
        }
    };

    for (int jt = blockIdx.x >> 2; jt < NJOBS; jt += 37) {
        const int n0 = jt * 128;

        float d[2][4][4];
        #pragma unroll
        for (int i = 0; i < 2; i++)
            #pragma unroll
            for (int j = 0; j < 4; j++)
                #pragma unroll
                for (int k2 = 0; k2 < 4; k2++) d[i][j][k2] = 0.f;

        ldg_B(n0, 0);
        sts_B(0);
        __syncthreads();

        #pragma unroll 1
        for (int c = 0; c < 16; c++) {
            int s = c & 1;
            if (c + 1 < 16) ldg_B(n0, c + 1);
            // compute slab c from stage s
            #pragma unroll
            for (int ks = 0; ks < 2; ks++) {
                const int kby = (c * 32 + ks * 16) * 2;     // A panel byte col
                uint32_t ah[2][4], al[2][4];
                #pragma unroll
                for (int mi = 0; mi < 2; mi++) {
                    int row = wm * 32 + mi * 16 + (lane & 15);
                    uint32_t off = row * APSTRB + kby + (lane >> 4) * 16;
                    ldsm4(ah[mi], sbase + APH_OFF + off);
                    ldsm4(al[mi], sbase + APL_OFF + off);
                }
                uint32_t bh[4][2], bl[4][2];
                #pragma unroll
                for (int nb = 0; nb < 2; nb++) {
                    int gq  = lane >> 3;
                    int row = wn * 32 + nb * 16 + (gq >> 1) * 8 + (lane & 7);
                    int kc  = ks * 32 + (gq & 1) * 16;
                    ldsm4(&bh[nb * 2][0], sbase + LBH_OFF(s) + row * ROWB + kc);
                    ldsm4(&bl[nb * 2][0], sbase + LBL_OFF(s) + row * ROWB + kc);
                }
                #pragma unroll
                for (int mi = 0; mi < 2; mi++)
                    #pragma unroll
                    for (int ni = 0; ni < 4; ni++) {
                        mma16816(d[mi][ni], ah[mi], bh[ni]);
                        mma16816(d[mi][ni], ah[mi], bl[ni]);
                        mma16816(d[mi][ni], al[mi], bh[ni]);
                    }
            }
            if (c + 1 < 16) {
                sts_B(1 - s);
            }
            __syncthreads();
        }

        // epilogue: direct scalar stores
        const int g  = lane >> 2;
        const int i2 = (lane & 3) * 2;
        #pragma unroll
        for (int mi = 0; mi < 2; mi++) {
            int r0 = m0 + wm * 32 + mi * 16 + g;
            long rb0 = (long)r0 * VOCAB;
            long rb1 = (long)(r0 + 8) * VOCAB;
            #pragma unroll
            for (int ni = 0; ni < 4; ni++) {
                int col = n0 + wn * 32 + ni * 8 + i2;
                if (col < VOCAB) {
                    out[rb0 + col] = d[mi][ni][0];
                    out[rb1 + col] = d[mi][ni][2];
                    if (col + 1 < VOCAB) {
                        out[rb0 + col + 1] = d[mi][ni][1];
                        out[rb1 + col + 1] = d[mi][ni][3];
                    }
                }
            }
        }
        __syncthreads();
    }
}

// ---------------------------------------------------------------------------
extern "C" void kernel_launch(void* const* d_in, const int* in_sizes, int n_in,
                              void* d_out, int out_size)
{
    const float* hidden = (const float*)d_in[0];
    const int*   tids   = (const int*)  d_in[1];
    const float* ip_w   = (const float*)d_in[2];
    const float* ip_b   = (const float*)d_in[3];
    const float* w_ih0  = (const float*)d_in[4];
    const float* w_hh0  = (const float*)d_in[5];
    const float* b_ih0  = (const float*)d_in[6];
    const float* b_hh0  = (const float*)d_in[7];
    const float* w_ih1  = (const float*)d_in[8];
    const float* w_hh1  = (const float*)d_in[9];
    const float* b_ih1  = (const float*)d_in[10];
    const float* b_hh1  = (const float*)d_in[11];
    const float* embed  = (const float*)d_in[12];
    const float* out_w  = (const float*)d_in[13];
    float* out = (float*)d_out;

    cudaFuncSetAttribute(logits_mma, cudaFuncAttributeMaxDynamicSharedMemorySize, LOGITS_SMEM);

    gru_fused<<<GRIDN, 256>>>(hidden, tids, ip_w, ip_b,
                              w_ih0, w_hh0, b_ih0, b_hh0,
                              w_ih1, w_hh1, b_ih1, b_hh1, embed);

    logits_mma<<<148, 256, LOGITS_SMEM>>>(out_w, out);
}

// round 9
// speedup vs baseline: 1.7119x; 1.7119x over previous
#include <cuda_runtime.h>
#include <cuda_fp16.h>
#include <math.h>
#include <stdint.h>

// ---------------------------------------------------------------------------
// ReDrafterHead: 2-layer GRU draft head + big vocab projection.
// B=64, HIDDEN=4096, DH=512, VOCAB=50257, NUM_DRAFT=4.
//
// Round 9:
//  - gru: revert to round-7 (fused epilogue, 2x3 utile, conflict-free banks);
//    epilogue now writes fp16 A (single array).
//  - logits: SINGLE fp16 mma term (rel-err budget 1e-3 >> fp16 dot err ~3e-4).
//    3x less tensor work, ~2.5x fewer ldsm, smem 30.7KB -> 3 CTAs/SM.
// ---------------------------------------------------------------------------

#define B_      64
#define HID     4096
#define DH      512
#define VOCAB   50257
#define NDRAFT  4
#define GRIDN   128

__device__ float g_h[2][2][B_ * DH];        // [layer][slot][b*DH+j]
__device__ float g_part[16 * B_ * DH];      // ip split-K partials
__device__ __half g_Ah[B_ * NDRAFT * DH];   // h2 rows fp16, m = b*4+step
__device__ unsigned int g_bcount;           // monotonic barrier counter

__device__ __forceinline__ float sigmoidf_(float v) { return 1.0f / (1.0f + __expf(-v)); }

__device__ __forceinline__ uint32_t pack_f16x2(__half lo, __half hi) {
    return ((uint32_t)__half_as_ushort(hi) << 16) | (uint32_t)__half_as_ushort(lo);
}
__device__ __forceinline__ uint32_t smem_to_u32(const void* p) {
    uint32_t a;
    asm("{ .reg .u64 t; cvta.to.shared.u64 t, %1; cvt.u32.u64 %0, t; }" : "=r"(a) : "l"(p));
    return a;
}
__device__ __forceinline__ void ldsm4(uint32_t* r, uint32_t addr) {
    asm volatile("ldmatrix.sync.aligned.m8n8.x4.shared.b16 {%0,%1,%2,%3}, [%4];"
        : "=r"(r[0]), "=r"(r[1]), "=r"(r[2]), "=r"(r[3]) : "r"(addr));
}
__device__ __forceinline__ void mma16816h(float* d, const uint32_t* a, const uint32_t* b) {
    asm volatile("mma.sync.aligned.m16n8k16.row.col.f32.f16.f16.f32 "
        "{%0,%1,%2,%3}, {%4,%5,%6,%7}, {%8,%9}, {%0,%1,%2,%3};"
        : "+f"(d[0]), "+f"(d[1]), "+f"(d[2]), "+f"(d[3])
        : "r"(a[0]), "r"(a[1]), "r"(a[2]), "r"(a[3]), "r"(b[0]), "r"(b[1]));
}

// Grid-wide barrier: monotonic counter (graph-replay safe; GRIDN co-resident).
__device__ __forceinline__ void grid_barrier(int tid) {
    __syncthreads();
    if (tid == 0) {
        __threadfence();
        unsigned int old = atomicAdd(&g_bcount, 1u);
        unsigned int target = (old / GRIDN + 1u) * GRIDN;
        unsigned int v;
        do {
            asm volatile("ld.acquire.gpu.global.u32 %0, [%1];" : "=r"(v) : "l"(&g_bcount));
        } while (v < target);
    }
    __syncthreads();
}

// ---------------------------------------------------------------------------
struct SmemIP { float As[32][64]; float Ws[32][64]; };
// A2 offset = 64*36*4 + 16 B -> bank sets disjoint from A1.
struct SmemG  { float A1[64][36]; float padA[4]; float A2[64][36];
                float W[24][36];  float epi[64][25]; };

// One GRU layer for one step. CTA owns j-range [jb, jb+4): GEMM 64 x 24 x 512
// (cols 0-11: gi {r,z,n} x 4j via Wih & A1; 12-23: gh via Whh & A2) + combine.
// a1mode: 0 = zeros, 1 = embed gather, 2 = pointer.
__device__ __forceinline__ void gates_layer(
    SmemG& s, const int* sTid, int tid, int jb,
    int a1mode, const float* A1g, const float* A2g, const float* embed,
    const float* Wih, const float* Whh,
    const float* bih, const float* bhh,
    const float* hOld, float* hNew,
    bool writeA, int step)
{
    const int mg = tid >> 3;               // 0..31
    const int r0 = mg * 2;                 // rows r0, r0+1
    const int g  = tid & 7;                // 0..7
    const int c0 = g * 3;                  // 0..21
    const float* As = (g < 4) ? &s.A1[0][0] : &s.A2[0][0];
    float acc[2][3] = {};

    float4 pA1[2], pA2[2], pW;
    const int frow = tid >> 3;
    const int fc4  = (tid & 7) * 4;
    const int wr   = tid >> 3;
    const int wrr  = (wr < 12) ? wr : wr - 12;
    const float* wbase = (wr < 12) ? Wih : Whh;
    const long  woff = (long)((wrr >> 2) * 512 + jb + (wrr & 3)) * DH + fc4;

    auto fetch = [&](int kt) {
        #pragma unroll
        for (int i = 0; i < 2; i++) {
            int row = frow + i * 32;
            if (a1mode == 0)      pA1[i] = make_float4(0.f, 0.f, 0.f, 0.f);
            else if (a1mode == 1) pA1[i] = *reinterpret_cast<const float4*>(
                                             &embed[(long)sTid[row] * DH + kt + fc4]);
            else                  pA1[i] = *reinterpret_cast<const float4*>(
                                             &A1g[row * DH + kt + fc4]);
            pA2[i] = *reinterpret_cast<const float4*>(&A2g[row * DH + kt + fc4]);
        }
        if (tid < 192)
            pW = *reinterpret_cast<const float4*>(&wbase[woff + kt]);
    };
    auto stage = [&]() {
        #pragma unroll
        for (int i = 0; i < 2; i++) {
            int row = frow + i * 32;
            *reinterpret_cast<float4*>(&s.A1[row][fc4]) = pA1[i];
            *reinterpret_cast<float4*>(&s.A2[row][fc4]) = pA2[i];
        }
        if (tid < 192)
            *reinterpret_cast<float4*>(&s.W[wr][fc4]) = pW;
    };

    fetch(0);
    for (int kt = 0; kt < DH; kt += 32) {
        __syncthreads();
        stage();
        __syncthreads();
        if (kt + 32 < DH) fetch(kt + 32);
        #pragma unroll
        for (int k = 0; k < 32; k += 4) {
            float4 w0 = *reinterpret_cast<const float4*>(&s.W[c0 + 0][k]);
            float4 w1 = *reinterpret_cast<const float4*>(&s.W[c0 + 1][k]);
            float4 w2 = *reinterpret_cast<const float4*>(&s.W[c0 + 2][k]);
            #pragma unroll
            for (int r = 0; r < 2; r++) {
                float4 a = *reinterpret_cast<const float4*>(&As[(r0 + r) * 36 + k]);
                acc[r][0] += a.x * w0.x + a.y * w0.y + a.z * w0.z + a.w * w0.w;
                acc[r][1] += a.x * w1.x + a.y * w1.y + a.z * w1.z + a.w * w1.w;
                acc[r][2] += a.x * w2.x + a.y * w2.y + a.z * w2.z + a.w * w2.w;
            }
        }
    }

    #pragma unroll
    for (int r = 0; r < 2; r++)
        #pragma unroll
        for (int cc = 0; cc < 3; cc++)
            s.epi[r0 + r][c0 + cc] = acc[r][cc];
    __syncthreads();
    {
        int m = tid >> 2, j = tid & 3, jj = jb + j;
        float gir = s.epi[m][j],      giz = s.epi[m][4 + j],  gin = s.epi[m][8 + j];
        float ghr = s.epi[m][12 + j], ghz = s.epi[m][16 + j], ghn = s.epi[m][20 + j];
        float r = sigmoidf_(gir + bih[jj]       + ghr + bhh[jj]);
        float z = sigmoidf_(giz + bih[512 + jj] + ghz + bhh[512 + jj]);
        float n = tanhf(gin + bih[1024 + jj] + r * (ghn + bhh[1024 + jj]));
        float hnew = (1.f - z) * n + z * hOld[m * DH + jj];
        hNew[m * DH + jj] = hnew;
        if (writeA)
            g_Ah[(m * NDRAFT + step) * DH + jj] = __float2half(hnew);
    }
}

// ---------------------------------------------------------------------------
__global__ __launch_bounds__(256) void gru_fused(
    const float* __restrict__ hidden, const int* __restrict__ tids,
    const float* __restrict__ ip_w,  const float* __restrict__ ip_b,
    const float* __restrict__ w_ih0, const float* __restrict__ w_hh0,
    const float* __restrict__ b_ih0, const float* __restrict__ b_hh0,
    const float* __restrict__ w_ih1, const float* __restrict__ w_hh1,
    const float* __restrict__ b_ih1, const float* __restrict__ b_hh1,
    const float* __restrict__ embed)
{
    __shared__ union { SmemIP ip; SmemG g; } sm;
    __shared__ int sTid[64];
    const int tid = threadIdx.x;
    const int c = blockIdx.x;

    // ---- phase 0: input projection partials (64x64 n-tile, 256-k slice) ----
    {
        const int n0 = (c & 7) * 64;
        const int kbase = (c >> 3) * 256;
        const int ty = tid >> 4, tx = tid & 15;
        float acc[4][4] = {};
        for (int kt = 0; kt < 256; kt += 32) {
            #pragma unroll
            for (int i = 0; i < 2; i++) {
                int f = tid + i * 256;
                int m = f >> 3;
                int kq = (f & 7) << 2;
                float4 va = *reinterpret_cast<const float4*>(&hidden[m * HID + kbase + kt + kq]);
                sm.ip.As[kq + 0][m] = va.x; sm.ip.As[kq + 1][m] = va.y;
                sm.ip.As[kq + 2][m] = va.z; sm.ip.As[kq + 3][m] = va.w;
                float4 vw = *reinterpret_cast<const float4*>(&ip_w[(n0 + m) * HID + kbase + kt + kq]);
                sm.ip.Ws[kq + 0][m] = vw.x; sm.ip.Ws[kq + 1][m] = vw.y;
                sm.ip.Ws[kq + 2][m] = vw.z; sm.ip.Ws[kq + 3][m] = vw.w;
            }
            __syncthreads();
            #pragma unroll
            for (int kk = 0; kk < 32; kk++) {
                float a[4], b[4];
                #pragma unroll
                for (int i = 0; i < 4; i++) { a[i] = sm.ip.As[kk][ty * 4 + i]; b[i] = sm.ip.Ws[kk][tx * 4 + i]; }
                #pragma unroll
                for (int i = 0; i < 4; i++)
                    #pragma unroll
                    for (int j = 0; j < 4; j++) acc[i][j] += a[i] * b[j];
            }
            __syncthreads();
        }
        float* part = g_part + (c >> 3) * (B_ * DH);
        #pragma unroll
        for (int i = 0; i < 4; i++)
            #pragma unroll
            for (int j = 0; j < 4; j++)
                part[(ty * 4 + i) * DH + n0 + tx * 4 + j] = acc[i][j];
    }
    grid_barrier(tid);

    // ---- phase 1: reduce 16 partials + bias ----
    {
        int idx = c * 256 + tid;
        float s = 0.f;
        #pragma unroll
        for (int p = 0; p < 16; p++) s += g_part[p * (B_ * DH) + idx];
        s += ip_b[idx & (DH - 1)];
        g_h[0][0][idx] = s;
        g_h[1][0][idx] = s;
    }
    grid_barrier(tid);

    // ---- 4 draft steps x 2 GRU layers ----
    const int jb = c * 4;
    for (int step = 0; step < NDRAFT; step++) {
        const int p = step & 1;
        if (step > 0 && tid < 64) sTid[tid] = tids[tid * NDRAFT + step - 1];
        __syncthreads();
        gates_layer(sm.g, sTid, tid, jb,
                    (step == 0) ? 0 : 1, nullptr, g_h[0][p], embed,
                    w_ih0, w_hh0, b_ih0, b_hh0,
                    g_h[0][p], g_h[0][1 - p], false, step);
        grid_barrier(tid);
        gates_layer(sm.g, sTid, tid, jb,
                    2, g_h[0][1 - p], g_h[1][p], embed,
                    w_ih1, w_hh1, b_ih1, b_hh1,
                    g_h[1][p], g_h[1][1 - p], true, step);
        grid_barrier(tid);
    }
}

// ---------------------------------------------------------------------------
// Logits GEMM via single fp16 mma.sync (fp32 accum).
// CTA tile 128(M) x 64(N) x 32(K); 8 warps (2 M x 4 N); warp tile 64x16.
// smem 30.7KB -> 3 CTAs/SM. grid (2, 786): m-half pairs share B via L2.
// ---------------------------------------------------------------------------
#define ROWB 80
#define AH_OFF(s) ((s) * 10240)
#define BH_OFF(s) (20480 + (s) * 5120)
#define LOGITS_SMEM 30720

__global__ __launch_bounds__(256, 3) void logits_mma(const float* __restrict__ W,
                                                     float* __restrict__ out)
{
    extern __shared__ char smem[];
    const uint32_t sbase = smem_to_u32(smem);
    const int tid  = threadIdx.x;
    const int lane = tid & 31;
    const int w    = tid >> 5;
    const int wm   = w >> 2;   // 0..1
    const int wn   = w & 3;    // 0..3
    const int m0   = blockIdx.x * 128;
    const int n0   = blockIdx.y * 64;

    float d[4][2][4];
    #pragma unroll
    for (int i = 0; i < 4; i++)
        #pragma unroll
        for (int j = 0; j < 2; j++)
            #pragma unroll
            for (int q = 0; q < 4; q++) d[i][j][q] = 0.f;

    float4 breg[2];

    auto cpasync_A = [&](int c, int s) {
        const int k0 = c * 32;
        #pragma unroll
        for (int i = 0; i < 2; i++) {
            int idx = tid + i * 256;         // 0..511
            int row = idx >> 2;              // 0..127
            int ch  = idx & 3;               // 16B chunk (8 halves)
            const __half* sh = &g_Ah[(m0 + row) * DH + k0 + ch * 8];
            uint32_t dh = sbase + AH_OFF(s) + row * ROWB + ch * 16;
            asm volatile("cp.async.ca.shared.global [%0], [%1], 16;" :: "r"(dh), "l"(sh));
        }
        asm volatile("cp.async.commit_group;" ::: "memory");
    };

    auto ldg_B = [&](int c) {
        const int k0 = c * 32;
        #pragma unroll
        for (int i = 0; i < 2; i++) {
            int idx = tid + i * 256;
            int row = idx >> 3;              // 0..63
            int col = (idx & 7) * 4;
            int vr = n0 + row;
            breg[i] = (vr < VOCAB)
                ? *reinterpret_cast<const float4*>(&W[(long)vr * DH + k0 + col])
                : make_float4(0.f, 0.f, 0.f, 0.f);
        }
    };

    auto sts_B = [&](int s) {
        #pragma unroll
        for (int i = 0; i < 2; i++) {
            int idx = tid + i * 256;
            int row = idx >> 3;
            int col = (idx & 7) * 4;
            float4 v = breg[i];
            uint2 ph;
            ph.x = pack_f16x2(__float2half(v.x), __float2half(v.y));
            ph.y = pack_f16x2(__float2half(v.z), __float2half(v.w));
            *reinterpret_cast<uint2*>(smem + BH_OFF(s) + row * ROWB + col * 2) = ph;
        }
    };

    auto compute = [&](int s) {
        #pragma unroll
        for (int ks = 0; ks < 2; ks++) {
            uint32_t ah[4][4];
            #pragma unroll
            for (int mi = 0; mi < 4; mi++) {
                int row = wm * 64 + mi * 16 + (lane & 15);
                int kc  = ks * 32 + (lane >> 4) * 16;
                ldsm4(ah[mi], sbase + AH_OFF(s) + row * ROWB + kc);
            }
            uint32_t bh[2][2];
            {
                int gq  = lane >> 3;
                int row = wn * 16 + (gq >> 1) * 8 + (lane & 7);
                int kc  = ks * 32 + (gq & 1) * 16;
                ldsm4(&bh[0][0], sbase + BH_OFF(s) + row * ROWB + kc);
            }
            #pragma unroll
            for (int mi = 0; mi < 4; mi++)
                #pragma unroll
                for (int ni = 0; ni < 2; ni++)
                    mma16816h(d[mi][ni], ah[mi], bh[ni]);
        }
    };

    cpasync_A(0, 0);
    ldg_B(0);
    sts_B(0);
    asm volatile("cp.async.wait_group 0;" ::: "memory");
    __syncthreads();

    #pragma unroll 1
    for (int c = 0; c < 16; c++) {
        int s = c & 1;
        if (c + 1 < 16) {
            cpasync_A(c + 1, 1 - s);
            ldg_B(c + 1);
        }
        compute(s);
        if (c + 1 < 16) {
            sts_B(1 - s);
            asm volatile("cp.async.wait_group 0;" ::: "memory");
        }
        __syncthreads();
    }

    const int g  = lane >> 2;
    const int i2 = (lane & 3) * 2;
    #pragma unroll
    for (int mi = 0; mi < 4; mi++) {
        int r0 = m0 + wm * 64 + mi * 16 + g;
        long rb0 = (long)r0 * VOCAB;
        long rb1 = (long)(r0 + 8) * VOCAB;
        #pragma unroll
        for (int ni = 0; ni < 2; ni++) {
            int col = n0 + wn * 16 + ni * 8 + i2;
            if (col < VOCAB) {
                out[rb0 + col] = d[mi][ni][0];
                out[rb1 + col] = d[mi][ni][2];
                if (col + 1 < VOCAB) {
                    out[rb0 + col + 1] = d[mi][ni][1];
                    out[rb1 + col + 1] = d[mi][ni][3];
                }
            }
        }
    }
}

// ---------------------------------------------------------------------------
extern "C" void kernel_launch(void* const* d_in, const int* in_sizes, int n_in,
                              void* d_out, int out_size)
{
    const float* hidden = (const float*)d_in[0];
    const int*   tids   = (const int*)  d_in[1];
    const float* ip_w   = (const float*)d_in[2];
    const float* ip_b   = (const float*)d_in[3];
    const float* w_ih0  = (const float*)d_in[4];
    const float* w_hh0  = (const float*)d_in[5];
    const float* b_ih0  = (const float*)d_in[6];
    const float* b_hh0  = (const float*)d_in[7];
    const float* w_ih1  = (const float*)d_in[8];
    const float* w_hh1  = (const float*)d_in[9];
    const float* b_ih1  = (const float*)d_in[10];
    const float* b_hh1  = (const float*)d_in[11];
    const float* embed  = (const float*)d_in[12];
    const float* out_w  = (const float*)d_in[13];
    float* out = (float*)d_out;

    cudaFuncSetAttribute(logits_mma, cudaFuncAttributeMaxDynamicSharedMemorySize, LOGITS_SMEM);

    gru_fused<<<GRIDN, 256>>>(hidden, tids, ip_w, ip_b,
                              w_ih0, w_hh0, b_ih0, b_hh0,
                              w_ih1, w_hh1, b_ih1, b_hh1, embed);

    logits_mma<<<dim3(2, (VOCAB + 63) / 64), 256, LOGITS_SMEM>>>(out_w, out);
}